// round 3
// baseline (speedup 1.0000x reference)
#include <cuda_runtime.h>
#include <cuda_bf16.h>

#define N_NODES_MAX 1000000
#define KE_HALF 7.199822675975274f   // 14.399645351950548 / 2

// Per-node precomputed table: .x = z (float), .y = z^p * d
__device__ float2 g_node[N_NODES_MAX];
// a0..a3, c0..c3 (c normalized)
__device__ float g_params[8];

__device__ __forceinline__ float softplus_f(float x) {
    // raw params are moderate (|x| < ~4); log1p(exp(x)) is stable enough here
    return log1pf(expf(x));
}

__global__ void prep_kernel(const int* __restrict__ species,
                            const int* __restrict__ index_to_z,
                            const float* __restrict__ a_raw,
                            const float* __restrict__ c_raw,
                            const float* __restrict__ p_raw,
                            const float* __restrict__ d_raw,
                            float* __restrict__ out,
                            int n_nodes) {
    int i = blockIdx.x * blockDim.x + threadIdx.x;

    if (i < 8) {
        if (i < 4) {
            g_params[i] = softplus_f(a_raw[i]);
        } else {
            float c0 = softplus_f(c_raw[0]);
            float c1 = softplus_f(c_raw[1]);
            float c2 = softplus_f(c_raw[2]);
            float c3 = softplus_f(c_raw[3]);
            float inv_s = 1.0f / (c0 + c1 + c2 + c3);
            g_params[i] = softplus_f(c_raw[i - 4]) * inv_s;
        }
    }

    if (i < n_nodes) {
        out[i] = 0.0f;  // output is poisoned by harness; zero for atomic accumulation
        float p = softplus_f(p_raw[0]);
        float d = softplus_f(d_raw[0]);
        float z = (float)index_to_z[species[i]];
        g_node[i] = make_float2(z, powf(z, p) * d);
    }
}

__device__ __forceinline__ float edge_energy(float dd, float cc, int si, int ri,
                                             float a0, float a1, float a2, float a3,
                                             float c0, float c1, float c2, float c3,
                                             float* __restrict__ out) {
    float2 ni = g_node[ri];
    float2 nj = g_node[si];

    // x = KE * cutoff * z_i * z_j / (dist + 1e-8), with KE/2 folded in
    float x = __fdividef(KE_HALF * cc * ni.x * nj.x, dd + 1e-8f);

    // rzd = dist * (z_i^p + z_j^p) * d  (d folded into node table)
    float rzd = dd * (ni.y + nj.y);

    float y = c0 * __expf(-a0 * rzd)
            + c1 * __expf(-a1 * rzd)
            + c2 * __expf(-a2 * rzd)
            + c3 * __expf(-a3 * rzd);

    // switch: w = sigma(1-s)/(sigma(1-s)+sigma(s)) = 1/(1+exp(1/s1 - 1/sd))
    float sd = dd * (1.0f / 1.5f);
    float s1 = 1.0f - sd;
    sd = fmaxf(sd, 1e-8f);
    s1 = fmaxf(s1, 1e-8f);
    float t = __expf(__fdividef(1.0f, s1) - __fdividef(1.0f, sd));
    float w = __fdividef(1.0f, 1.0f + t);   // sd tiny -> t=0 -> w=1 ; s1 tiny -> t=inf -> w=0

    float e = w * x * y;
    atomicAdd(&out[ri], e);
    return e;
}

__global__ __launch_bounds__(256)
void edge_kernel(const float4* __restrict__ dist4,
                 const float4* __restrict__ cut4,
                 const int4* __restrict__ snd4,
                 const int4* __restrict__ rcv4,
                 float* __restrict__ out,
                 int n4, int n_tail_base, int n_edges) {
    int i = blockIdx.x * blockDim.x + threadIdx.x;

    // broadcast params (L1/L2 hit)
    float a0 = g_params[0], a1 = g_params[1], a2 = g_params[2], a3 = g_params[3];
    float c0 = g_params[4], c1 = g_params[5], c2 = g_params[6], c3 = g_params[7];

    if (i < n4) {
        float4 dv = dist4[i];
        float4 cv = cut4[i];
        int4   sv = snd4[i];
        int4   rv = rcv4[i];

        edge_energy(dv.x, cv.x, sv.x, rv.x, a0,a1,a2,a3, c0,c1,c2,c3, out);
        edge_energy(dv.y, cv.y, sv.y, rv.y, a0,a1,a2,a3, c0,c1,c2,c3, out);
        edge_energy(dv.z, cv.z, sv.z, rv.z, a0,a1,a2,a3, c0,c1,c2,c3, out);
        edge_energy(dv.w, cv.w, sv.w, rv.w, a0,a1,a2,a3, c0,c1,c2,c3, out);
    }

    // tail (n_edges not divisible by 4) — handled by thread 0 scalar
    if (i == 0 && n_tail_base < n_edges) {
        const float* dist = (const float*)dist4;
        const float* cut  = (const float*)cut4;
        const int*   snd  = (const int*)snd4;
        const int*   rcv  = (const int*)rcv4;
        for (int e = n_tail_base; e < n_edges; e++) {
            edge_energy(dist[e], cut[e], snd[e], rcv[e], a0,a1,a2,a3, c0,c1,c2,c3, out);
        }
    }
}

extern "C" void kernel_launch(void* const* d_in, const int* in_sizes, int n_in,
                              void* d_out, int out_size) {
    const int*   node_species = (const int*)d_in[0];
    const float* distances    = (const float*)d_in[1];
    const float* cutoffs      = (const float*)d_in[2];
    const int*   senders      = (const int*)d_in[3];
    const int*   receivers    = (const int*)d_in[4];
    const int*   index_to_z   = (const int*)d_in[5];
    const float* a_raw        = (const float*)d_in[6];
    const float* c_raw        = (const float*)d_in[7];
    const float* p_raw        = (const float*)d_in[8];
    const float* d_raw        = (const float*)d_in[9];
    float* out = (float*)d_out;

    int n_nodes = in_sizes[0];
    int n_edges = in_sizes[1];

    {
        int threads = 256;
        int blocks = (n_nodes + threads - 1) / threads;
        prep_kernel<<<blocks, threads>>>(node_species, index_to_z,
                                         a_raw, c_raw, p_raw, d_raw,
                                         out, n_nodes);
    }
    {
        int n4 = n_edges >> 2;
        int threads = 256;
        int blocks = (n4 + threads - 1) / threads;
        if (blocks == 0) blocks = 1;
        edge_kernel<<<blocks, threads>>>((const float4*)distances,
                                         (const float4*)cutoffs,
                                         (const int4*)senders,
                                         (const int4*)receivers,
                                         out, n4, n4 << 2, n_edges);
    }
}